// round 1
// baseline (speedup 1.0000x reference)
#include <cuda_runtime.h>

#define BATCH   1024
#define TOT     4096
#define SEN     1024
#define CNNOUT  3264
#define NOUT    1968
#define LORAR   64

// ---------------- scratch (static device globals; no allocations) ------------
__device__ __align__(256) float g_feat[BATCH * CNNOUT];   // 13.4 MB
__device__ __align__(256) float g_weff[TOT * TOT];        // 64 MB
__device__ __align__(256) float g_sA[BATCH * TOT];        // 16 MB
__device__ __align__(256) float g_sB[BATCH * TOT];        // 16 MB
__device__ __align__(256) float g_O[BATCH * 1024];        // 4 MB

// ---------------- zero ------------------------------------------------------
__global__ void zero_kernel(float* __restrict__ p, int n) {
    int i = blockIdx.x * blockDim.x + threadIdx.x;
    if (i < n) p[i] = 0.0f;
}

// ---------------- conv feature extraction -----------------------------------
struct ConvPtrs { const float* w[8]; };

__global__ void conv_feat_kernel(const float* __restrict__ x, ConvPtrs cw,
                                 const float* __restrict__ conv_b,
                                 float* __restrict__ feat)
{
    __shared__ float xs[512];                  // x[b] : [h][w][c] (NHWC)
    const int b = blockIdx.x;
    const float* xb = x + b * 512;
    for (int i = threadIdx.x; i < 512; i += 256) xs[i] = xb[i];
    __syncthreads();

    const int offs[9] = {0, 1024, 1808, 2384, 2784, 3040, 3184, 3248, 3264};

    for (int o = threadIdx.x; o < CNNOUT; o += 256) {
        int k = 1;
        while (o >= offs[k]) k++;              // conv with kernel size k (1..8)
        int local = o - offs[k - 1];
        int H = 9 - k;
        int f = local / (H * H);
        int rem = local - f * H * H;
        int i0 = rem / H;
        int j0 = rem - i0 * H;

        const float* w = cw.w[k - 1] + f * 8 * k * k;   // (FN,C,k,k)
        float acc = conv_b[(k - 1) * 16 + f];
        for (int c = 0; c < 8; c++) {
            const float* wc = w + c * k * k;
            for (int p = 0; p < k; p++)
                for (int q = 0; q < k; q++)
                    acc += xs[((i0 + p) * 8 + (j0 + q)) * 8 + c] * wc[p * k + q];
        }
        feat[b * CNNOUT + o] = fmaxf(acc, 0.0f);
    }
}

// ---------------- W_eff = (W + 2 * A@B) * (W != 0) ---------------------------
__global__ void build_weff_kernel(const float* __restrict__ W,
                                  const float* __restrict__ lA,
                                  const float* __restrict__ lB,
                                  float* __restrict__ Weff)
{
    __shared__ float Ash[64][65];   // [k][row]
    __shared__ float Bsh[64][64];   // [k][col]
    const int row0 = blockIdx.y * 64;
    const int col0 = blockIdx.x * 64;
    const int tid  = threadIdx.x;

    for (int l = tid; l < 64 * 16; l += 256) {          // lora_A rows
        int r  = l >> 4;
        int k4 = (l & 15) << 2;
        float4 v = *(const float4*)(lA + (row0 + r) * LORAR + k4);
        Ash[k4 + 0][r] = v.x; Ash[k4 + 1][r] = v.y;
        Ash[k4 + 2][r] = v.z; Ash[k4 + 3][r] = v.w;
    }
    for (int l = tid; l < 64 * 16; l += 256) {          // lora_B cols
        int k  = l >> 4;
        int c4 = (l & 15) << 2;
        *(float4*)&Bsh[k][c4] = *(const float4*)(lB + k * TOT + col0 + c4);
    }
    __syncthreads();

    const int ty = tid >> 4, tx = tid & 15;
    float acc[4][4] = {};
    for (int k = 0; k < 64; k++) {
        float a[4], bb[4];
#pragma unroll
        for (int i = 0; i < 4; i++) a[i]  = Ash[k][ty * 4 + i];
#pragma unroll
        for (int j = 0; j < 4; j++) bb[j] = Bsh[k][tx * 4 + j];
#pragma unroll
        for (int i = 0; i < 4; i++)
#pragma unroll
            for (int j = 0; j < 4; j++) acc[i][j] += a[i] * bb[j];
    }
#pragma unroll
    for (int i = 0; i < 4; i++) {
        int r = row0 + ty * 4 + i;
#pragma unroll
        for (int j = 0; j < 4; j++) {
            int c = col0 + tx * 4 + j;
            float w = W[r * TOT + c];
            Weff[r * TOT + c] = (w == 0.0f) ? 0.0f : (w + 2.0f * acc[i][j]);
        }
    }
}

// ---------------- generic fp32 SGEMM: C = epi(A @ B) -------------------------
// BM=BN=128, BK=8, 256 threads, 8x8 per thread.  M is exact multiple of 128.
template<bool HAS_BIAS, bool HAS_ADD, bool RELU, bool NGUARD>
__global__ __launch_bounds__(256)
void sgemm_kernel(const float* __restrict__ A, const float* __restrict__ Bm,
                  float* __restrict__ C,
                  const float* __restrict__ bias,
                  const float* __restrict__ addend,
                  int N, int K, int lda, int ldb, int ldc, int ldadd)
{
    __shared__ float As[8][128];
    __shared__ float Bs[8][128];

    const int tid  = threadIdx.x;
    const int row0 = blockIdx.y * 128;
    const int col0 = blockIdx.x * 128;

    const int arow = tid >> 1;            // 0..127
    const int acol = (tid & 1) << 2;      // 0 / 4
    const int brow = tid >> 5;            // 0..7
    const int bcol = (tid & 31) << 2;     // 0..124

    const float* Aptr = A + (size_t)(row0 + arow) * lda + acol;
    const float* Bptr = Bm + (size_t)brow * ldb + col0 + bcol;
    const bool  bok   = !NGUARD || (col0 + bcol) < N;

    const int ty = tid >> 4, tx = tid & 15;

    float acc[8][8];
#pragma unroll
    for (int i = 0; i < 8; i++)
#pragma unroll
        for (int j = 0; j < 8; j++) acc[i][j] = 0.0f;

    for (int k0 = 0; k0 < K; k0 += 8) {
        float4 av = *(const float4*)(Aptr);
        Aptr += 8;
        float4 bv = make_float4(0.f, 0.f, 0.f, 0.f);
        if (bok) bv = *(const float4*)(Bptr);
        Bptr += (size_t)8 * ldb;

        As[acol + 0][arow] = av.x; As[acol + 1][arow] = av.y;
        As[acol + 2][arow] = av.z; As[acol + 3][arow] = av.w;
        *(float4*)&Bs[brow][bcol] = bv;
        __syncthreads();

#pragma unroll
        for (int kk = 0; kk < 8; kk++) {
            float a[8], b[8];
            *(float4*)&a[0] = *(const float4*)&As[kk][ty * 8 + 0];
            *(float4*)&a[4] = *(const float4*)&As[kk][ty * 8 + 4];
            *(float4*)&b[0] = *(const float4*)&Bs[kk][tx * 8 + 0];
            *(float4*)&b[4] = *(const float4*)&Bs[kk][tx * 8 + 4];
#pragma unroll
            for (int i = 0; i < 8; i++)
#pragma unroll
                for (int j = 0; j < 8; j++) acc[i][j] += a[i] * b[j];
        }
        __syncthreads();
    }

#pragma unroll
    for (int i = 0; i < 8; i++) {
        const int r = row0 + ty * 8 + i;
#pragma unroll
        for (int j = 0; j < 8; j++) {
            const int c = col0 + tx * 8 + j;
            if (NGUARD && c >= N) continue;
            float v = acc[i][j];
            if (HAS_BIAS) v += bias[c];
            if (HAS_ADD)  v += addend[(size_t)r * ldadd + c];
            if (RELU)     v = fmaxf(v, 0.0f);
            C[(size_t)r * ldc + c] = v;
        }
    }
}

// ---------------- launch ----------------------------------------------------
extern "C" void kernel_launch(void* const* d_in, const int* in_sizes, int n_in,
                              void* d_out, int out_size)
{
    const float* x      = (const float*)d_in[0];
    ConvPtrs cw;
    for (int i = 0; i < 8; i++) cw.w[i] = (const float*)d_in[1 + i];
    const float* conv_b = (const float*)d_in[9];
    const float* W      = (const float*)d_in[10];
    const float* lora_A = (const float*)d_in[11];
    const float* lora_B = (const float*)d_in[12];
    const float* ip_w   = (const float*)d_in[13];
    const float* ip_b   = (const float*)d_in[14];
    const float* out_w  = (const float*)d_in[15];
    const float* out_b  = (const float*)d_in[16];
    float* out = (float*)d_out;

    float *feat, *weff, *sA, *sB, *Obuf;
    cudaGetSymbolAddress((void**)&feat, g_feat);
    cudaGetSymbolAddress((void**)&weff, g_weff);
    cudaGetSymbolAddress((void**)&sA,   g_sA);
    cudaGetSymbolAddress((void**)&sB,   g_sB);
    cudaGetSymbolAddress((void**)&Obuf, g_O);

    // 1. state_A = 0 (E-GEMM fills cols [0,1024); rest must be zero)
    {
        int n = BATCH * TOT;
        zero_kernel<<<(n + 255) / 256, 256>>>(sA, n);
    }
    // 2. conv features
    conv_feat_kernel<<<BATCH, 256>>>(x, cw, conv_b, feat);
    // 3. W_eff
    build_weff_kernel<<<dim3(TOT / 64, TOT / 64), 256>>>(W, lora_A, lora_B, weff);

    // 4. state_A[:, :1024] = relu(feat @ ip_w + ip_b)   (t = 0)
    sgemm_kernel<true, false, true, false><<<dim3(SEN / 128, BATCH / 128), 256>>>(
        feat, ip_w, sA, ip_b, nullptr, SEN, CNNOUT, CNNOUT, SEN, TOT, 0);

    // 5. t=1: state nonzero only in first 1024 cols -> K = 1024
    sgemm_kernel<false, true, true, false><<<dim3(TOT / 128, BATCH / 128), 256>>>(
        sA, weff, sB, nullptr, sA, TOT, SEN, TOT, TOT, TOT, TOT);

    // 6. t=2
    sgemm_kernel<false, true, true, false><<<dim3(TOT / 128, BATCH / 128), 256>>>(
        sB, weff, sA, nullptr, sB, TOT, TOT, TOT, TOT, TOT, TOT);

    // 7. t=3
    sgemm_kernel<false, true, true, false><<<dim3(TOT / 128, BATCH / 128), 256>>>(
        sA, weff, sB, nullptr, sA, TOT, TOT, TOT, TOT, TOT, TOT);

    // 8. t=4: only output cols [3072, 4096) are consumed downstream
    sgemm_kernel<false, true, true, false><<<dim3(1024 / 128, BATCH / 128), 256>>>(
        sB, weff + 3072, Obuf, nullptr, sB + 3072, 1024, TOT, TOT, TOT, 1024, TOT);

    // 9. out = O @ out_w + out_b   (N = 1968 needs guard)
    sgemm_kernel<true, false, false, true><<<dim3((NOUT + 127) / 128, BATCH / 128), 256>>>(
        Obuf, out_w, out, out_b, nullptr, NOUT, 1024, 1024, NOUT, NOUT, 0);
}

// round 3
// speedup vs baseline: 2.4728x; 2.4728x over previous
#include <cuda_runtime.h>
#include <cuda_bf16.h>
#include <cstdint>

#define BATCH    1024
#define TOT      4096
#define SEN      1024
#define CNNOUT   3264
#define NOUT     1968
#define NOUT_PAD 2048

// ---------------- scratch device globals (no allocations) -------------------
__device__ __align__(256) __nv_bfloat16 g_featH[(size_t)BATCH * CNNOUT];
__device__ __align__(256) __nv_bfloat16 g_featL[(size_t)BATCH * CNNOUT];
__device__ __align__(256) __nv_bfloat16 g_ipwH [(size_t)SEN * CNNOUT];
__device__ __align__(256) __nv_bfloat16 g_ipwL [(size_t)SEN * CNNOUT];
__device__ __align__(256) __nv_bfloat16 g_WH   [(size_t)TOT * TOT];
__device__ __align__(256) __nv_bfloat16 g_WL   [(size_t)TOT * TOT];
__device__ __align__(256) __nv_bfloat16 g_owH  [(size_t)NOUT_PAD * 1024];
__device__ __align__(256) __nv_bfloat16 g_owL  [(size_t)NOUT_PAD * 1024];
__device__ __align__(256) __nv_bfloat16 g_P0H  [(size_t)BATCH * TOT];
__device__ __align__(256) __nv_bfloat16 g_P0L  [(size_t)BATCH * TOT];
__device__ __align__(256) __nv_bfloat16 g_P1H  [(size_t)BATCH * TOT];
__device__ __align__(256) __nv_bfloat16 g_P1L  [(size_t)BATCH * TOT];
__device__ __align__(256) __nv_bfloat16 g_OPH  [(size_t)BATCH * 1024];
__device__ __align__(256) __nv_bfloat16 g_OPL  [(size_t)BATCH * 1024];
__device__ __align__(256) float g_F0[(size_t)BATCH * TOT];
__device__ __align__(256) float g_F1[(size_t)BATCH * TOT];

// ---------------- helpers ----------------------------------------------------
__device__ __forceinline__ uint32_t smem_u32(const void* p) {
    uint32_t a;
    asm("{ .reg .u64 t; cvta.to.shared.u64 t, %1; cvt.u32.u64 %0, t; }" : "=r"(a) : "l"(p));
    return a;
}
__device__ __forceinline__ void cpa(uint32_t dst, const void* src) {
    asm volatile("cp.async.cg.shared.global [%0], [%1], 16;" :: "r"(dst), "l"(src));
}
#define CP_COMMIT() asm volatile("cp.async.commit_group;")
#define CP_WAIT2()  asm volatile("cp.async.wait_group 2;")

__device__ __forceinline__ void ldsm4(uint32_t* r, uint32_t addr) {
    asm volatile("ldmatrix.sync.aligned.m8n8.x4.shared.b16 {%0,%1,%2,%3}, [%4];"
                 : "=r"(r[0]), "=r"(r[1]), "=r"(r[2]), "=r"(r[3]) : "r"(addr));
}
__device__ __forceinline__ void mma16816(float* c, const uint32_t* a, const uint32_t* b) {
    asm volatile("mma.sync.aligned.m16n8k16.row.col.f32.bf16.bf16.f32 "
                 "{%0,%1,%2,%3}, {%4,%5,%6,%7}, {%8,%9}, {%0,%1,%2,%3};"
                 : "+f"(c[0]), "+f"(c[1]), "+f"(c[2]), "+f"(c[3])
                 : "r"(a[0]), "r"(a[1]), "r"(a[2]), "r"(a[3]), "r"(b[0]), "r"(b[1]));
}

// split fp32 -> bf16 hi/lo, 8 at a time
__device__ __forceinline__ void split8(const float* v, uint4& uh, uint4& ul) {
    uint32_t h[4], l[4];
#pragma unroll
    for (int q = 0; q < 4; q++) {
        __nv_bfloat16 b0 = __float2bfloat16(v[2 * q]);
        __nv_bfloat16 b1 = __float2bfloat16(v[2 * q + 1]);
        float r0 = v[2 * q]     - __bfloat162float(b0);
        float r1 = v[2 * q + 1] - __bfloat162float(b1);
        __nv_bfloat16 c0 = __float2bfloat16(r0);
        __nv_bfloat16 c1 = __float2bfloat16(r1);
        h[q] = (uint32_t)__bfloat16_as_ushort(b0) | ((uint32_t)__bfloat16_as_ushort(b1) << 16);
        l[q] = (uint32_t)__bfloat16_as_ushort(c0) | ((uint32_t)__bfloat16_as_ushort(c1) << 16);
    }
    uh = make_uint4(h[0], h[1], h[2], h[3]);
    ul = make_uint4(l[0], l[1], l[2], l[3]);
}

// ---------------- conv feature extraction -> hi/lo row-major ----------------
struct ConvPtrs { const float* w[8]; };

__global__ void conv_feat_kernel(const float* __restrict__ x, ConvPtrs cw,
                                 const float* __restrict__ conv_b,
                                 __nv_bfloat16* __restrict__ fH,
                                 __nv_bfloat16* __restrict__ fL)
{
    __shared__ float xs[512];
    const int b = blockIdx.x;
    const float* xb = x + b * 512;
    for (int i = threadIdx.x; i < 512; i += 256) xs[i] = xb[i];
    __syncthreads();

    const int offs[9] = {0, 1024, 1808, 2384, 2784, 3040, 3184, 3248, 3264};

    for (int o = threadIdx.x; o < CNNOUT; o += 256) {
        int k = 1;
        while (o >= offs[k]) k++;
        int local = o - offs[k - 1];
        int H = 9 - k;
        int f = local / (H * H);
        int rem = local - f * H * H;
        int i0 = rem / H;
        int j0 = rem - i0 * H;

        const float* w = cw.w[k - 1] + f * 8 * k * k;
        float acc = conv_b[(k - 1) * 16 + f];
        for (int c = 0; c < 8; c++) {
            const float* wc = w + c * k * k;
            for (int p = 0; p < k; p++)
                for (int q = 0; q < k; q++)
                    acc += xs[((i0 + p) * 8 + (j0 + q)) * 8 + c] * wc[p * k + q];
        }
        float e = fmaxf(acc, 0.0f);
        __nv_bfloat16 bh = __float2bfloat16(e);
        __nv_bfloat16 bl = __float2bfloat16(e - __bfloat162float(bh));
        fH[(size_t)b * CNNOUT + o] = bh;
        fL[(size_t)b * CNNOUT + o] = bl;
    }
}

// ---------------- pack [K,N] fp32 weight transposed -> [N,K] hi/lo bf16 -----
__global__ __launch_bounds__(256) void pack_wT(const float* __restrict__ w,
                                               int ldw, int ntrue, int ldk,
                                               __nv_bfloat16* __restrict__ H,
                                               __nv_bfloat16* __restrict__ L)
{
    __shared__ float sm[64 * 65];
    const int k0 = blockIdx.x * 64, n0 = blockIdx.y * 64;
    const int tid = threadIdx.x;

    for (int i = tid; i < 4096; i += 256) {
        int k = i >> 6, n = i & 63;
        int gn = n0 + n;
        sm[k * 65 + n] = (gn < ntrue) ? w[(size_t)(k0 + k) * ldw + gn] : 0.0f;
    }
    __syncthreads();

    for (int it = tid; it < 512; it += 256) {
        int n = it & 63, kg = it >> 6;
        float v[8];
#pragma unroll
        for (int j = 0; j < 8; j++) v[j] = sm[(kg * 8 + j) * 65 + n];
        uint4 uh, ul;
        split8(v, uh, ul);
        size_t o = (size_t)(n0 + n) * ldk + k0 + kg * 8;
        *(uint4*)((char*)H + o * 2) = uh;
        *(uint4*)((char*)L + o * 2) = ul;
    }
}

// ---------------- W_eff build -> transposed hi/lo ---------------------------
__global__ __launch_bounds__(256) void build_weff(const float* __restrict__ W,
                                                  const float* __restrict__ lA,
                                                  const float* __restrict__ lB,
                                                  __nv_bfloat16* __restrict__ WtH,
                                                  __nv_bfloat16* __restrict__ WtL)
{
    __shared__ float sm[2 * 64 * 65];
    float* Ash = sm;             // [k][r]
    float* Bsh = sm + 64 * 65;   // [k][c]

    const int row0 = blockIdx.y * 64;   // source-row (K of recurrence)
    const int col0 = blockIdx.x * 64;   // source-col (N of recurrence)
    const int tid  = threadIdx.x;

    for (int l = tid; l < 64 * 16; l += 256) {
        int r = l >> 4, k4 = (l & 15) << 2;
        float4 v = *(const float4*)(lA + (size_t)(row0 + r) * 64 + k4);
        Ash[(k4 + 0) * 65 + r] = v.x; Ash[(k4 + 1) * 65 + r] = v.y;
        Ash[(k4 + 2) * 65 + r] = v.z; Ash[(k4 + 3) * 65 + r] = v.w;
    }
    for (int l = tid; l < 64 * 16; l += 256) {
        int k = l >> 4, c4 = (l & 15) << 2;
        *(float4*)&Bsh[k * 64 + c4] = *(const float4*)(lB + (size_t)k * TOT + col0 + c4);
    }
    __syncthreads();

    const int ty = tid >> 4, tx = tid & 15;
    float acc[4][4] = {};
    for (int k = 0; k < 64; k++) {
        float a[4], bb[4];
#pragma unroll
        for (int i = 0; i < 4; i++) a[i] = Ash[k * 65 + ty * 4 + i];
#pragma unroll
        for (int j = 0; j < 4; j++) bb[j] = Bsh[k * 64 + tx * 4 + j];
#pragma unroll
        for (int i = 0; i < 4; i++)
#pragma unroll
            for (int j = 0; j < 4; j++) acc[i][j] += a[i] * bb[j];
    }
    __syncthreads();

    float* S   = sm;             // lora part [k][n]
    float* Wsh = sm + 64 * 65;   // W [k][n]
#pragma unroll
    for (int i = 0; i < 4; i++)
#pragma unroll
        for (int j = 0; j < 4; j++)
            S[(ty * 4 + i) * 65 + tx * 4 + j] = acc[i][j];
    for (int l = tid; l < 64 * 64; l += 256) {
        int k = l >> 6, n = l & 63;
        Wsh[k * 65 + n] = W[(size_t)(row0 + k) * TOT + col0 + n];
    }
    __syncthreads();

    for (int it = tid; it < 512; it += 256) {
        int n = it & 63, kg = it >> 6;
        float v[8];
#pragma unroll
        for (int j = 0; j < 8; j++) {
            float w = Wsh[(kg * 8 + j) * 65 + n];
            float s = S[(kg * 8 + j) * 65 + n];
            v[j] = (w == 0.0f) ? 0.0f : (w + 2.0f * s);
        }
        uint4 uh, ul;
        split8(v, uh, ul);
        size_t o = (size_t)(col0 + n) * TOT + row0 + kg * 8;   // transposed
        *(uint4*)((char*)WtH + o * 2) = uh;
        *(uint4*)((char*)WtL + o * 2) = ul;
    }
}

// ---------------- mma.sync bf16-split GEMM ----------------------------------
// C[128 x 128 per CTA] = (AH+AL) @ (BH+BL)^T  (drop AL*BL), fp32 accum.
// A row-major [M][lda], B row-major [N][ldb] (i.e. B^T k-contiguous).
// Epilogue: +bias, +addend (col-limited), relu; write fp32 and/or hi/lo pack.
#define STG_B 65536
__global__ __launch_bounds__(256, 1)
void mma_gemm(const __nv_bfloat16* __restrict__ AH, const __nv_bfloat16* __restrict__ AL, int lda,
              const __nv_bfloat16* __restrict__ BH, const __nv_bfloat16* __restrict__ BL, int ldb,
              int K,
              const float* __restrict__ bias,
              const float* __restrict__ addend, int add_cols, int ld_add,
              int do_relu,
              float* __restrict__ outF, int ldF, int ncolF,
              __nv_bfloat16* __restrict__ PH, __nv_bfloat16* __restrict__ PL, int ldP)
{
    extern __shared__ __align__(128) char smc[];
    const int tid = threadIdx.x, l = tid & 31, wid = tid >> 5;
    const int nblk = blockIdx.x, mblk = blockIdx.y;
    const int KB = K >> 6;
    const uint32_t smb = smem_u32(smc);

    const int mrow0 = mblk * 128;
    const int nrow0 = nblk * 128;

    // ---- async tile loader: 4 matrices x 128 rows x 8 granules of 16B ----
    auto load_stage = [&](int s, int c) {
        const size_t kof = (size_t)c * 64;
#pragma unroll
        for (int it = 0; it < 4; it++) {
            int idx = tid + it * 256;
            int r = idx >> 3, g = idx & 7;
            uint32_t soff = (uint32_t)r * 128 + ((uint32_t)(g ^ (r & 7)) << 4);
            uint32_t dst = smb + (uint32_t)s * STG_B + soff;
            size_t ka = (size_t)(mrow0 + r) * lda + kof + g * 8;
            size_t kb = (size_t)(nrow0 + r) * ldb + kof + g * 8;
            cpa(dst,          AH + ka);
            cpa(dst + 16384,  AL + ka);
            cpa(dst + 32768,  BH + kb);
            cpa(dst + 49152,  BL + kb);
        }
    };

    const int mw = wid & 1, nw = wid >> 1;
    const int mbase = mw * 64, nbase = nw * 32;
    const int rA0 = mbase + (l & 7) + ((l >> 3) & 1) * 8;
    const int rB0 = nbase + (l & 7) + ((l >> 3) & 1) * 8;
    const int gsel = l >> 4;
    const uint32_t l7x = (uint32_t)(l & 7);

    float acc[4][4][4];
#pragma unroll
    for (int a = 0; a < 4; a++)
#pragma unroll
        for (int b = 0; b < 4; b++)
#pragma unroll
            for (int c = 0; c < 4; c++) acc[a][b][c] = 0.0f;

    load_stage(0, 0); CP_COMMIT();
    load_stage(1, 1); CP_COMMIT();

    for (int c = 0; c < KB; c++) {
        const int s = c % 3;
        if (c + 2 < KB) load_stage((c + 2) % 3, c + 2);
        CP_COMMIT();
        CP_WAIT2();
        __syncthreads();

        const uint32_t base = smb + (uint32_t)s * STG_B;
#pragma unroll
        for (int kk = 0; kk < 4; kk++) {
            const uint32_t g = 2 * kk + gsel;
            const uint32_t sw = ((g ^ l7x) << 4);

            uint32_t bh[4][2], bl_[4][2];
#pragma unroll
            for (int p = 0; p < 2; p++) {
                uint32_t t[4];
                uint32_t addr = base + 32768 + (uint32_t)(rB0 + p * 16) * 128 + sw;
                ldsm4(t, addr);
                bh[p * 2][0] = t[0]; bh[p * 2][1] = t[2];
                bh[p * 2 + 1][0] = t[1]; bh[p * 2 + 1][1] = t[3];
                ldsm4(t, addr + 16384);
                bl_[p * 2][0] = t[0]; bl_[p * 2][1] = t[2];
                bl_[p * 2 + 1][0] = t[1]; bl_[p * 2 + 1][1] = t[3];
            }
            uint32_t ah[4][4], al_[4][4];
#pragma unroll
            for (int mt = 0; mt < 4; mt++) {
                uint32_t addr = base + (uint32_t)(rA0 + mt * 16) * 128 + sw;
                ldsm4(ah[mt], addr);
                ldsm4(al_[mt], addr + 16384);
            }
#pragma unroll
            for (int mt = 0; mt < 4; mt++)
#pragma unroll
                for (int nt = 0; nt < 4; nt++) {
                    mma16816(acc[mt][nt], ah[mt], bh[nt]);
                    mma16816(acc[mt][nt], ah[mt], bl_[nt]);
                    mma16816(acc[mt][nt], al_[mt], bh[nt]);
                }
        }
        __syncthreads();
    }

    // ---- epilogue ----
    const int rr = l >> 2, cc = (l & 3) * 2;
    const int growb = mrow0 + mbase;
    const int gcolb = nrow0 + nbase;

#pragma unroll
    for (int mt = 0; mt < 4; mt++)
#pragma unroll
        for (int h = 0; h < 2; h++) {
            const int r = growb + mt * 16 + rr + h * 8;
#pragma unroll
            for (int nt = 0; nt < 4; nt++) {
                const int cx = gcolb + nt * 8 + cc;
                float v0 = acc[mt][nt][h * 2 + 0];
                float v1 = acc[mt][nt][h * 2 + 1];
                if (bias && cx < ncolF) {
                    float2 bv = *(const float2*)(bias + cx);
                    v0 += bv.x; v1 += bv.y;
                }
                if (addend && cx < add_cols) {
                    float2 av = *(const float2*)(addend + (size_t)r * ld_add + cx);
                    v0 += av.x; v1 += av.y;
                }
                if (do_relu) { v0 = fmaxf(v0, 0.0f); v1 = fmaxf(v1, 0.0f); }
                if (outF && cx < ncolF)
                    *(float2*)(outF + (size_t)r * ldF + cx) = make_float2(v0, v1);
                if (PH) {
                    __nv_bfloat16 h0 = __float2bfloat16(v0);
                    __nv_bfloat16 h1 = __float2bfloat16(v1);
                    __nv_bfloat16 q0 = __float2bfloat16(v0 - __bfloat162float(h0));
                    __nv_bfloat16 q1 = __float2bfloat16(v1 - __bfloat162float(h1));
                    uint32_t ph = (uint32_t)__bfloat16_as_ushort(h0) | ((uint32_t)__bfloat16_as_ushort(h1) << 16);
                    uint32_t pl = (uint32_t)__bfloat16_as_ushort(q0) | ((uint32_t)__bfloat16_as_ushort(q1) << 16);
                    *(uint32_t*)((char*)PH + ((size_t)r * ldP + cx) * 2) = ph;
                    *(uint32_t*)((char*)PL + ((size_t)r * ldP + cx) * 2) = pl;
                }
            }
        }
}

// ---------------- launch ----------------------------------------------------
extern "C" void kernel_launch(void* const* d_in, const int* in_sizes, int n_in,
                              void* d_out, int out_size)
{
    const float* x      = (const float*)d_in[0];
    ConvPtrs cw;
    for (int i = 0; i < 8; i++) cw.w[i] = (const float*)d_in[1 + i];
    const float* conv_b = (const float*)d_in[9];
    const float* W      = (const float*)d_in[10];
    const float* lora_A = (const float*)d_in[11];
    const float* lora_B = (const float*)d_in[12];
    const float* ip_w   = (const float*)d_in[13];
    const float* ip_b   = (const float*)d_in[14];
    const float* out_w  = (const float*)d_in[15];
    const float* out_b  = (const float*)d_in[16];
    float* out = (float*)d_out;

    __nv_bfloat16 *featH, *featL, *ipwH, *ipwL, *WH, *WL, *owH, *owL;
    __nv_bfloat16 *P0H, *P0L, *P1H, *P1L, *OPH, *OPL;
    float *F0, *F1;
    cudaGetSymbolAddress((void**)&featH, g_featH);
    cudaGetSymbolAddress((void**)&featL, g_featL);
    cudaGetSymbolAddress((void**)&ipwH,  g_ipwH);
    cudaGetSymbolAddress((void**)&ipwL,  g_ipwL);
    cudaGetSymbolAddress((void**)&WH,    g_WH);
    cudaGetSymbolAddress((void**)&WL,    g_WL);
    cudaGetSymbolAddress((void**)&owH,   g_owH);
    cudaGetSymbolAddress((void**)&owL,   g_owL);
    cudaGetSymbolAddress((void**)&P0H,   g_P0H);
    cudaGetSymbolAddress((void**)&P0L,   g_P0L);
    cudaGetSymbolAddress((void**)&P1H,   g_P1H);
    cudaGetSymbolAddress((void**)&P1L,   g_P1L);
    cudaGetSymbolAddress((void**)&OPH,   g_OPH);
    cudaGetSymbolAddress((void**)&OPL,   g_OPL);
    cudaGetSymbolAddress((void**)&F0,    g_F0);
    cudaGetSymbolAddress((void**)&F1,    g_F1);

    const int SMEM_DYN = 3 * STG_B;   // 192 KB
    cudaFuncSetAttribute(mma_gemm, cudaFuncAttributeMaxDynamicSharedMemorySize, SMEM_DYN);

    // 1. conv features -> hi/lo
    conv_feat_kernel<<<BATCH, 256>>>(x, cw, conv_b, featH, featL);
    // 2. ip_w [3264,1024] -> ipwT [1024][3264]
    pack_wT<<<dim3(CNNOUT / 64, SEN / 64), 256>>>(ip_w, SEN, SEN, CNNOUT, ipwH, ipwL);
    // 3. out_w [1024,1968] -> owT [2048][1024] (rows >=1968 zero)
    pack_wT<<<dim3(1024 / 64, NOUT_PAD / 64), 256>>>(out_w, NOUT, NOUT, 1024, owH, owL);
    // 4. W_eff -> WT [4096][4096]
    build_weff<<<dim3(TOT / 64, TOT / 64), 256>>>(W, lora_A, lora_B, WH, WL);

    // 5. t0: state0 = relu(feat @ ip_w + b)  -> F0 (cols<1024), P0
    mma_gemm<<<dim3(SEN / 128, BATCH / 128), 256, SMEM_DYN>>>(
        featH, featL, CNNOUT, ipwH, ipwL, CNNOUT, CNNOUT,
        ip_b, nullptr, 0, 0, 1, F0, TOT, SEN, P0H, P0L, TOT);

    // 6. t1: K = 1024 (state0 cols >=1024 are zero)
    mma_gemm<<<dim3(TOT / 128, BATCH / 128), 256, SMEM_DYN>>>(
        P0H, P0L, TOT, WH, WL, TOT, 1024,
        nullptr, F0, 1024, TOT, 1, F1, TOT, TOT, P1H, P1L, TOT);

    // 7. t2
    mma_gemm<<<dim3(TOT / 128, BATCH / 128), 256, SMEM_DYN>>>(
        P1H, P1L, TOT, WH, WL, TOT, TOT,
        nullptr, F1, TOT, TOT, 1, F0, TOT, TOT, P0H, P0L, TOT);

    // 8. t3
    mma_gemm<<<dim3(TOT / 128, BATCH / 128), 256, SMEM_DYN>>>(
        P0H, P0L, TOT, WH, WL, TOT, TOT,
        nullptr, F0, TOT, TOT, 1, F1, TOT, TOT, P1H, P1L, TOT);

    // 9. t4: only N = cols [3072,4096) feed the output head
    mma_gemm<<<dim3(1024 / 128, BATCH / 128), 256, SMEM_DYN>>>(
        P1H, P1L, TOT, WH + (size_t)3072 * TOT, WL + (size_t)3072 * TOT, TOT, TOT,
        nullptr, F1 + 3072, 1024, TOT, 1, nullptr, 0, 0, OPH, OPL, 1024);

    // 10. out = O @ out_w + out_b  (N padded 2048, store-guard 1968)
    mma_gemm<<<dim3(NOUT_PAD / 128, BATCH / 128), 256, SMEM_DYN>>>(
        OPH, OPL, 1024, owH, owL, 1024, 1024,
        out_b, nullptr, 0, 0, 0, out, NOUT, NOUT, nullptr, nullptr, 0);
}

// round 4
// speedup vs baseline: 2.5544x; 1.0330x over previous
#include <cuda_runtime.h>
#include <cuda_bf16.h>
#include <cstdint>

#define BATCH    1024
#define TOT      4096
#define SEN      1024
#define CNNOUT   3264
#define NOUT     1968
#define NOUT_PAD 2048

// ---------------- scratch device globals (no allocations) -------------------
__device__ __align__(256) __nv_bfloat16 g_featH[(size_t)BATCH * CNNOUT];
__device__ __align__(256) __nv_bfloat16 g_featL[(size_t)BATCH * CNNOUT];
__device__ __align__(256) __nv_bfloat16 g_ipwH [(size_t)SEN * CNNOUT];
__device__ __align__(256) __nv_bfloat16 g_ipwL [(size_t)SEN * CNNOUT];
__device__ __align__(256) __nv_bfloat16 g_WH   [(size_t)TOT * TOT];
__device__ __align__(256) __nv_bfloat16 g_WL   [(size_t)TOT * TOT];
__device__ __align__(256) __nv_bfloat16 g_owH  [(size_t)NOUT_PAD * 1024];
__device__ __align__(256) __nv_bfloat16 g_owL  [(size_t)NOUT_PAD * 1024];
__device__ __align__(256) __nv_bfloat16 g_P0H  [(size_t)BATCH * TOT];
__device__ __align__(256) __nv_bfloat16 g_P0L  [(size_t)BATCH * TOT];
__device__ __align__(256) __nv_bfloat16 g_P1H  [(size_t)BATCH * TOT];
__device__ __align__(256) __nv_bfloat16 g_P1L  [(size_t)BATCH * TOT];
__device__ __align__(256) __nv_bfloat16 g_OPH  [(size_t)BATCH * 1024];
__device__ __align__(256) __nv_bfloat16 g_OPL  [(size_t)BATCH * 1024];
__device__ __align__(256) __nv_bfloat16 g_laH [(size_t)TOT * 64];
__device__ __align__(256) __nv_bfloat16 g_laL [(size_t)TOT * 64];
__device__ __align__(256) __nv_bfloat16 g_lbtH[(size_t)TOT * 64];
__device__ __align__(256) __nv_bfloat16 g_lbtL[(size_t)TOT * 64];

// ---------------- helpers ----------------------------------------------------
__device__ __forceinline__ uint32_t smem_u32(const void* p) {
    uint32_t a;
    asm("{ .reg .u64 t; cvta.to.shared.u64 t, %1; cvt.u32.u64 %0, t; }" : "=r"(a) : "l"(p));
    return a;
}
__device__ __forceinline__ void cpa(uint32_t dst, const void* src) {
    asm volatile("cp.async.cg.shared.global [%0], [%1], 16;" :: "r"(dst), "l"(src));
}
#define CP_COMMIT() asm volatile("cp.async.commit_group;")
#define CP_WAIT0()  asm volatile("cp.async.wait_group 0;")
#define CP_WAIT1()  asm volatile("cp.async.wait_group 1;")

__device__ __forceinline__ void ldsm4(uint32_t* r, uint32_t addr) {
    asm volatile("ldmatrix.sync.aligned.m8n8.x4.shared.b16 {%0,%1,%2,%3}, [%4];"
                 : "=r"(r[0]), "=r"(r[1]), "=r"(r[2]), "=r"(r[3]) : "r"(addr));
}
__device__ __forceinline__ void mma16816(float* c, const uint32_t* a, const uint32_t* b) {
    asm volatile("mma.sync.aligned.m16n8k16.row.col.f32.bf16.bf16.f32 "
                 "{%0,%1,%2,%3}, {%4,%5,%6,%7}, {%8,%9}, {%0,%1,%2,%3};"
                 : "+f"(c[0]), "+f"(c[1]), "+f"(c[2]), "+f"(c[3])
                 : "r"(a[0]), "r"(a[1]), "r"(a[2]), "r"(a[3]), "r"(b[0]), "r"(b[1]));
}

__device__ __forceinline__ void split8(const float* v, uint4& uh, uint4& ul) {
    uint32_t h[4], l[4];
#pragma unroll
    for (int q = 0; q < 4; q++) {
        __nv_bfloat16 b0 = __float2bfloat16(v[2 * q]);
        __nv_bfloat16 b1 = __float2bfloat16(v[2 * q + 1]);
        float r0 = v[2 * q]     - __bfloat162float(b0);
        float r1 = v[2 * q + 1] - __bfloat162float(b1);
        __nv_bfloat16 c0 = __float2bfloat16(r0);
        __nv_bfloat16 c1 = __float2bfloat16(r1);
        h[q] = (uint32_t)__bfloat16_as_ushort(b0) | ((uint32_t)__bfloat16_as_ushort(b1) << 16);
        l[q] = (uint32_t)__bfloat16_as_ushort(c0) | ((uint32_t)__bfloat16_as_ushort(c1) << 16);
    }
    uh = make_uint4(h[0], h[1], h[2], h[3]);
    ul = make_uint4(l[0], l[1], l[2], l[3]);
}
__device__ __forceinline__ void pack2(float v0, float v1, uint32_t& ph, uint32_t& pl) {
    __nv_bfloat16 h0 = __float2bfloat16(v0);
    __nv_bfloat16 h1 = __float2bfloat16(v1);
    __nv_bfloat16 q0 = __float2bfloat16(v0 - __bfloat162float(h0));
    __nv_bfloat16 q1 = __float2bfloat16(v1 - __bfloat162float(h1));
    ph = (uint32_t)__bfloat16_as_ushort(h0) | ((uint32_t)__bfloat16_as_ushort(h1) << 16);
    pl = (uint32_t)__bfloat16_as_ushort(q0) | ((uint32_t)__bfloat16_as_ushort(q1) << 16);
}
__device__ __forceinline__ float bflo(uint32_t u) {
    return __bfloat162float(__ushort_as_bfloat16((unsigned short)(u & 0xFFFF)));
}
__device__ __forceinline__ float bfhi(uint32_t u) {
    return __bfloat162float(__ushort_as_bfloat16((unsigned short)(u >> 16)));
}

// ---------------- conv feature extraction -> hi/lo row-major ----------------
struct ConvPtrs { const float* w[8]; };

__global__ void conv_feat_kernel(const float* __restrict__ x, ConvPtrs cw,
                                 const float* __restrict__ conv_b,
                                 __nv_bfloat16* __restrict__ fH,
                                 __nv_bfloat16* __restrict__ fL)
{
    __shared__ float xs[512];
    const int b = blockIdx.x;
    const float* xb = x + b * 512;
    for (int i = threadIdx.x; i < 512; i += 256) xs[i] = xb[i];
    __syncthreads();

    const int offs[9] = {0, 1024, 1808, 2384, 2784, 3040, 3184, 3248, 3264};

    for (int o = threadIdx.x; o < CNNOUT; o += 256) {
        int k = 1;
        while (o >= offs[k]) k++;
        int local = o - offs[k - 1];
        int H = 9 - k;
        int f = local / (H * H);
        int rem = local - f * H * H;
        int i0 = rem / H;
        int j0 = rem - i0 * H;

        const float* w = cw.w[k - 1] + f * 8 * k * k;
        float acc = conv_b[(k - 1) * 16 + f];
        for (int c = 0; c < 8; c++) {
            const float* wc = w + c * k * k;
            for (int p = 0; p < k; p++)
                for (int q = 0; q < k; q++)
                    acc += xs[((i0 + p) * 8 + (j0 + q)) * 8 + c] * wc[p * k + q];
        }
        float e = fmaxf(acc, 0.0f);
        __nv_bfloat16 bh = __float2bfloat16(e);
        __nv_bfloat16 bl = __float2bfloat16(e - __bfloat162float(bh));
        fH[(size_t)b * CNNOUT + o] = bh;
        fL[(size_t)b * CNNOUT + o] = bl;
    }
}

// ---------------- pack [K,N] fp32 weight transposed -> [N,K] hi/lo bf16 -----
__global__ __launch_bounds__(256) void pack_wT(const float* __restrict__ w,
                                               int ldw, int ntrue, int ldk,
                                               __nv_bfloat16* __restrict__ H,
                                               __nv_bfloat16* __restrict__ L)
{
    __shared__ float sm[64 * 65];
    const int k0 = blockIdx.x * 64, n0 = blockIdx.y * 64;
    const int tid = threadIdx.x;

    for (int i = tid; i < 4096; i += 256) {
        int k = i >> 6, n = i & 63;
        int gn = n0 + n;
        sm[k * 65 + n] = (gn < ntrue) ? w[(size_t)(k0 + k) * ldw + gn] : 0.0f;
    }
    __syncthreads();

    for (int it = tid; it < 512; it += 256) {
        int n = it & 63, kg = it >> 6;
        float v[8];
#pragma unroll
        for (int j = 0; j < 8; j++) v[j] = sm[(kg * 8 + j) * 65 + n];
        uint4 uh, ul;
        split8(v, uh, ul);
        size_t o = (size_t)(n0 + n) * ldk + k0 + kg * 8;
        *(uint4*)((char*)H + o * 2) = uh;
        *(uint4*)((char*)L + o * 2) = ul;
    }
}

// ---------------- straight split-copy fp32 -> hi/lo bf16 --------------------
__global__ void split_copy(const float* __restrict__ in,
                           __nv_bfloat16* __restrict__ H,
                           __nv_bfloat16* __restrict__ L, int n8)
{
    int i = blockIdx.x * blockDim.x + threadIdx.x;
    if (i >= n8) return;
    float v[8];
    *(float4*)(v)     = *(const float4*)(in + (size_t)i * 8);
    *(float4*)(v + 4) = *(const float4*)(in + (size_t)i * 8 + 4);
    uint4 uh, ul;
    split8(v, uh, ul);
    *(uint4*)((char*)H + (size_t)i * 16) = uh;
    *(uint4*)((char*)L + (size_t)i * 16) = ul;
}

// ---------------- mma.sync bf16-split GEMM ----------------------------------
// Tile: 128 x (NT*32).  3-term split (drop lo*lo).  Warps 2(M) x 4(N).
// WEFF mode: acc = lora product; epilogue = mask(W) * (W + 2*acc) -> packed Wt.
template<int NT, int STAGES, bool WEFF>
__global__ __launch_bounds__(256, 1)
void mma_gemm(const __nv_bfloat16* __restrict__ AH, const __nv_bfloat16* __restrict__ AL, int lda,
              const __nv_bfloat16* __restrict__ BH, const __nv_bfloat16* __restrict__ BL, int ldb,
              int K,
              const float* __restrict__ bias,
              const __nv_bfloat16* __restrict__ addH, const __nv_bfloat16* __restrict__ addL,
              int add_cols, int ld_add, int do_relu,
              float* __restrict__ outF, int ldF, int ncolF,
              __nv_bfloat16* __restrict__ PH, __nv_bfloat16* __restrict__ PL, int ldP,
              const float* __restrict__ Wsrc)
{
    constexpr int NTILE = NT * 32;
    constexpr int BLOFF = NTILE * 128;          // bytes of B-hi block
    constexpr int STG_BYTES = 32768 + 2 * BLOFF;
    extern __shared__ __align__(128) char smc[];

    const int tid = threadIdx.x, l = tid & 31, wid = tid >> 5;
    const int nblk = blockIdx.x, mblk = blockIdx.y;
    const int KB = K >> 6;
    const uint32_t smb = smem_u32(smc);
    const int mrow0 = mblk * 128;
    const int nrow0 = nblk * NTILE;

    auto load_stage = [&](int s, int c) {
        const int kof = c * 64;
        const uint32_t sb = smb + (uint32_t)s * STG_BYTES;
#pragma unroll
        for (int it = 0; it < 8; it++) {                      // A: 2048 granules
            int idx = tid + it * 256;
            int half = idx >> 10;
            int r = (idx & 1023) >> 3, g = idx & 7;
            uint32_t soff = (uint32_t)r * 128 + ((uint32_t)(g ^ (r & 7)) << 4);
            const __nv_bfloat16* src = (half ? AL : AH) + (size_t)(mrow0 + r) * lda + kof + g * 8;
            cpa(sb + (uint32_t)half * 16384 + soff, src);
        }
#pragma unroll
        for (int it = 0; it < NTILE / 16; it++) {             // B: NTILE*16 granules
            int idx = tid + it * 256;
            int half = idx >= NTILE * 8;
            int j = idx - half * NTILE * 8;
            int r = j >> 3, g = j & 7;
            uint32_t soff = (uint32_t)r * 128 + ((uint32_t)(g ^ (r & 7)) << 4);
            const __nv_bfloat16* src = (half ? BL : BH) + (size_t)(nrow0 + r) * ldb + kof + g * 8;
            cpa(sb + 32768 + (uint32_t)half * BLOFF + soff, src);
        }
    };

    const int mw = wid & 1, nw = wid >> 1;
    const int mbase = mw * 64, nbase = nw * (NT * 8);
    const int rA0 = mbase + (l & 7) + ((l >> 3) & 1) * 8;
    const int rB0 = nbase + (l & 7) + ((l >> 3) & 1) * 8;
    const int gsel = l >> 4;
    const uint32_t l7x = (uint32_t)(l & 7);

    float acc[4][NT][4];
#pragma unroll
    for (int a = 0; a < 4; a++)
#pragma unroll
        for (int b = 0; b < NT; b++)
#pragma unroll
            for (int c = 0; c < 4; c++) acc[a][b][c] = 0.0f;

    load_stage(0, 0);
    CP_COMMIT();
    if (STAGES == 3) {
        if (KB > 1) load_stage(1, 1);
        CP_COMMIT();
    }

    for (int c = 0; c < KB; c++) {
        const int s = c % STAGES;
        if (STAGES == 3) { CP_WAIT1(); } else { CP_WAIT0(); }
        __syncthreads();
        if (c + STAGES - 1 < KB) load_stage((c + STAGES - 1) % STAGES, c + STAGES - 1);
        CP_COMMIT();

        const uint32_t base = smb + (uint32_t)s * STG_BYTES;
#pragma unroll
        for (int kk = 0; kk < 4; kk++) {
            const uint32_t g = 2 * kk + gsel;
            const uint32_t sw = ((g ^ l7x) << 4);

            uint32_t ah[4][4], al_[4][4];
#pragma unroll
            for (int mt = 0; mt < 4; mt++) {
                uint32_t addr = base + (uint32_t)(rA0 + mt * 16) * 128 + sw;
                ldsm4(ah[mt], addr);
                ldsm4(al_[mt], addr + 16384);
            }
#pragma unroll
            for (int p = 0; p < NT / 2; p++) {
                uint32_t t0[4], t1[4];
                uint32_t addr = base + 32768 + (uint32_t)(rB0 + p * 16) * 128 + sw;
                ldsm4(t0, addr);
                ldsm4(t1, addr + BLOFF);
                uint32_t bh0[2] = {t0[0], t0[2]}, bh1[2] = {t0[1], t0[3]};
                uint32_t bl0[2] = {t1[0], t1[2]}, bl1[2] = {t1[1], t1[3]};
#pragma unroll
                for (int mt = 0; mt < 4; mt++) {
                    mma16816(acc[mt][2 * p],     ah[mt],  bh0);
                    mma16816(acc[mt][2 * p],     ah[mt],  bl0);
                    mma16816(acc[mt][2 * p],     al_[mt], bh0);
                    mma16816(acc[mt][2 * p + 1], ah[mt],  bh1);
                    mma16816(acc[mt][2 * p + 1], ah[mt],  bl1);
                    mma16816(acc[mt][2 * p + 1], al_[mt], bh1);
                }
            }
        }
    }

    const int rr = l >> 2, cc = (l & 3) * 2;

    if (WEFF) {
        // acc[mt][nt] = (lora_A @ lora_B)[kk=col][n=row].  Load W tile transposed.
        __syncthreads();
        float* Wt = (float*)smc;   // [n_local][kk_local], stride 129
        for (int i = tid; i < 128 * 128; i += 256) {
            int kk = i >> 7, n = i & 127;
            Wt[n * 129 + kk] = Wsrc[(size_t)(nrow0 + kk) * TOT + mrow0 + n];
        }
        __syncthreads();
#pragma unroll
        for (int mt = 0; mt < 4; mt++)
#pragma unroll
            for (int h = 0; h < 2; h++) {
                const int rl = mbase + mt * 16 + rr + h * 8;
                const size_t r = (size_t)(mrow0 + rl);
#pragma unroll
                for (int nt = 0; nt < NT; nt++) {
                    const int cl = nbase + nt * 8 + cc;
                    const int cx = nrow0 + cl;
                    float w0 = Wt[rl * 129 + cl];
                    float w1 = Wt[rl * 129 + cl + 1];
                    float v0 = (w0 == 0.0f) ? 0.0f : (w0 + 2.0f * acc[mt][nt][h * 2 + 0]);
                    float v1 = (w1 == 0.0f) ? 0.0f : (w1 + 2.0f * acc[mt][nt][h * 2 + 1]);
                    uint32_t ph, pl;
                    pack2(v0, v1, ph, pl);
                    *(uint32_t*)((char*)PH + (r * ldP + cx) * 2) = ph;
                    *(uint32_t*)((char*)PL + (r * ldP + cx) * 2) = pl;
                }
            }
        return;
    }

    const int growb = mrow0 + mbase;
    const int gcolb = nrow0 + nbase;
#pragma unroll
    for (int mt = 0; mt < 4; mt++)
#pragma unroll
        for (int h = 0; h < 2; h++) {
            const int r = growb + mt * 16 + rr + h * 8;
#pragma unroll
            for (int nt = 0; nt < NT; nt++) {
                const int cx = gcolb + nt * 8 + cc;
                float v0 = acc[mt][nt][h * 2 + 0];
                float v1 = acc[mt][nt][h * 2 + 1];
                if (bias && cx < ncolF) {
                    float2 bv = *(const float2*)(bias + cx);
                    v0 += bv.x; v1 += bv.y;
                }
                if (addH && cx < add_cols) {
                    uint32_t uh = *(const uint32_t*)((const char*)addH + ((size_t)r * ld_add + cx) * 2);
                    uint32_t ul = *(const uint32_t*)((const char*)addL + ((size_t)r * ld_add + cx) * 2);
                    v0 += bflo(uh) + bflo(ul);
                    v1 += bfhi(uh) + bfhi(ul);
                }
                if (do_relu) { v0 = fmaxf(v0, 0.0f); v1 = fmaxf(v1, 0.0f); }
                if (outF && cx < ncolF)
                    *(float2*)(outF + (size_t)r * ldF + cx) = make_float2(v0, v1);
                if (PH) {
                    uint32_t ph, pl;
                    pack2(v0, v1, ph, pl);
                    *(uint32_t*)((char*)PH + ((size_t)r * ldP + cx) * 2) = ph;
                    *(uint32_t*)((char*)PL + ((size_t)r * ldP + cx) * 2) = pl;
                }
            }
        }
}

// ---------------- launch ----------------------------------------------------
extern "C" void kernel_launch(void* const* d_in, const int* in_sizes, int n_in,
                              void* d_out, int out_size)
{
    const float* x      = (const float*)d_in[0];
    ConvPtrs cw;
    for (int i = 0; i < 8; i++) cw.w[i] = (const float*)d_in[1 + i];
    const float* conv_b = (const float*)d_in[9];
    const float* W      = (const float*)d_in[10];
    const float* lora_A = (const float*)d_in[11];
    const float* lora_B = (const float*)d_in[12];
    const float* ip_w   = (const float*)d_in[13];
    const float* ip_b   = (const float*)d_in[14];
    const float* out_w  = (const float*)d_in[15];
    const float* out_b  = (const float*)d_in[16];
    float* out = (float*)d_out;

    __nv_bfloat16 *featH, *featL, *ipwH, *ipwL, *WH, *WL, *owH, *owL;
    __nv_bfloat16 *P0H, *P0L, *P1H, *P1L, *OPH, *OPL, *laH, *laL, *lbtH, *lbtL;
    cudaGetSymbolAddress((void**)&featH, g_featH);
    cudaGetSymbolAddress((void**)&featL, g_featL);
    cudaGetSymbolAddress((void**)&ipwH,  g_ipwH);
    cudaGetSymbolAddress((void**)&ipwL,  g_ipwL);
    cudaGetSymbolAddress((void**)&WH,    g_WH);
    cudaGetSymbolAddress((void**)&WL,    g_WL);
    cudaGetSymbolAddress((void**)&owH,   g_owH);
    cudaGetSymbolAddress((void**)&owL,   g_owL);
    cudaGetSymbolAddress((void**)&P0H,   g_P0H);
    cudaGetSymbolAddress((void**)&P0L,   g_P0L);
    cudaGetSymbolAddress((void**)&P1H,   g_P1H);
    cudaGetSymbolAddress((void**)&P1L,   g_P1L);
    cudaGetSymbolAddress((void**)&OPH,   g_OPH);
    cudaGetSymbolAddress((void**)&OPL,   g_OPL);
    cudaGetSymbolAddress((void**)&laH,   g_laH);
    cudaGetSymbolAddress((void**)&laL,   g_laL);
    cudaGetSymbolAddress((void**)&lbtH,  g_lbtH);
    cudaGetSymbolAddress((void**)&lbtL,  g_lbtL);

    const int SMEM4 = 3 * (32768 + 2 * 128 * 128);   // 196608
    const int SMEM8 = 2 * (32768 + 2 * 256 * 128);   // 196608
    cudaFuncSetAttribute(mma_gemm<4, 3, false>, cudaFuncAttributeMaxDynamicSharedMemorySize, SMEM4);
    cudaFuncSetAttribute(mma_gemm<8, 2, false>, cudaFuncAttributeMaxDynamicSharedMemorySize, SMEM8);
    cudaFuncSetAttribute(mma_gemm<4, 3, true>,  cudaFuncAttributeMaxDynamicSharedMemorySize, SMEM4);

    // ---- prologue packs ----
    conv_feat_kernel<<<BATCH, 256>>>(x, cw, conv_b, featH, featL);
    pack_wT<<<dim3(CNNOUT / 64, SEN / 64), 256>>>(ip_w, SEN, SEN, CNNOUT, ipwH, ipwL);
    pack_wT<<<dim3(1024 / 64, NOUT_PAD / 64), 256>>>(out_w, NOUT, NOUT, 1024, owH, owL);
    split_copy<<<(TOT * 64 / 8 + 255) / 256, 256>>>(lora_A, laH, laL, TOT * 64 / 8);
    pack_wT<<<dim3(1, TOT / 64), 256>>>(lora_B, TOT, TOT, 64, lbtH, lbtL);

    // ---- W_eff^T (tensor-core lora product + fused mask/pack) ----
    mma_gemm<4, 3, true><<<dim3(32, 32), 256, SMEM4>>>(
        lbtH, lbtL, 64, laH, laL, 64, 64,
        nullptr, nullptr, nullptr, 0, 0, 0,
        nullptr, 0, 0, WH, WL, TOT, W);

    // ---- t0: state0 = relu(feat @ ip_w + b) -> P0 (cols < 1024) ----
    mma_gemm<4, 3, false><<<dim3(SEN / 128, 8), 256, SMEM4>>>(
        featH, featL, CNNOUT, ipwH, ipwL, CNNOUT, CNNOUT,
        ip_b, nullptr, nullptr, 0, 0, 1,
        nullptr, 0, SEN, P0H, P0L, TOT, nullptr);

    // ---- t1 (K = 1024) ----
    mma_gemm<8, 2, false><<<dim3(TOT / 256, 8), 256, SMEM8>>>(
        P0H, P0L, TOT, WH, WL, TOT, 1024,
        nullptr, P0H, P0L, 1024, TOT, 1,
        nullptr, 0, 0, P1H, P1L, TOT, nullptr);

    // ---- t2 ----
    mma_gemm<8, 2, false><<<dim3(TOT / 256, 8), 256, SMEM8>>>(
        P1H, P1L, TOT, WH, WL, TOT, TOT,
        nullptr, P1H, P1L, TOT, TOT, 1,
        nullptr, 0, 0, P0H, P0L, TOT, nullptr);

    // ---- t3 ----
    mma_gemm<8, 2, false><<<dim3(TOT / 256, 8), 256, SMEM8>>>(
        P0H, P0L, TOT, WH, WL, TOT, TOT,
        nullptr, P0H, P0L, TOT, TOT, 1,
        nullptr, 0, 0, P1H, P1L, TOT, nullptr);

    // ---- t4 (N = 1024: only cols [3072,4096) feed the head) ----
    mma_gemm<4, 3, false><<<dim3(1024 / 128, 8), 256, SMEM4>>>(
        P1H, P1L, TOT, WH + (size_t)3072 * TOT, WL + (size_t)3072 * TOT, TOT, TOT,
        nullptr, P1H + 3072, P1L + 3072, 1024, TOT, 1,
        nullptr, 0, 0, OPH, OPL, 1024, nullptr);

    // ---- out = O @ out_w + out_b ----
    mma_gemm<4, 3, false><<<dim3(NOUT_PAD / 128, 8), 256, SMEM4>>>(
        OPH, OPL, 1024, owH, owL, 1024, 1024,
        out_b, nullptr, nullptr, 0, 0, 0,
        out, NOUT, NOUT, nullptr, nullptr, 0, nullptr);
}